// round 5
// baseline (speedup 1.0000x reference)
#include <cuda_runtime.h>
#include <cstdint>

#define PP 2048
#define HH 1024
#define AA 16
#define OO 4

#define BM 128
#define BN 128
#define BK 32
#define NST 3

// SMEM per stage (floats): A 128x36 padded, B 32x132 padded
#define ASZ (128 * 36)
#define BSZ (32 * 132)
#define SMEM_FLOATS (NST * (ASZ + BSZ))
#define SMEM_BYTES  (SMEM_FLOATS * 4)

// ---------------- device scratch ----------------
__device__ float g_Xg [PP * HH];
__device__ float g_X1g[PP * HH];
__device__ float g_W  [3ll * AA * HH * HH];            // tf32-rounded W1,W2,W3
__device__ float g_Z  [(long long)AA * PP * HH];
__device__ float g_gw [AA * HH * OO];
__device__ float g_Gco[AA * OO];
__device__ float g_Bco[AA * OO];
__device__ float g_part[(long long)AA * 8 * PP * 8];   // [a][ntile 0..7][p][8]

// ---------------- helpers ----------------
__device__ __forceinline__ uint32_t smem_u32(const void* p) {
    uint32_t a;
    asm("{ .reg .u64 t; cvta.to.shared.u64 t, %1; cvt.u32.u64 %0, t; }" : "=r"(a) : "l"(p));
    return a;
}
__device__ __forceinline__ void cp16(uint32_t s, const void* g) {
    asm volatile("cp.async.cg.shared.global [%0], [%1], 16;" :: "r"(s), "l"(g));
}
__device__ __forceinline__ void cp_commit() {
    asm volatile("cp.async.commit_group;" ::: "memory");
}
template <int N>
__device__ __forceinline__ void cp_wait() {
    asm volatile("cp.async.wait_group %0;" :: "n"(N) : "memory");
}
__device__ __forceinline__ float f2tf_f(float v) {
    uint32_t r;
    asm("cvt.rna.tf32.f32 %0, %1;" : "=r"(r) : "f"(v));
    return __uint_as_float(r);
}
__device__ __forceinline__ void mma_tf32(float c[4], const uint32_t a[4], const uint32_t b[2]) {
    asm volatile(
        "mma.sync.aligned.m16n8k8.row.col.f32.tf32.tf32.f32 "
        "{%0,%1,%2,%3}, {%4,%5,%6,%7}, {%8,%9}, {%0,%1,%2,%3};"
        : "+f"(c[0]), "+f"(c[1]), "+f"(c[2]), "+f"(c[3])
        : "r"(a[0]), "r"(a[1]), "r"(a[2]), "r"(a[3]), "r"(b[0]), "r"(b[1]));
}

// ---------------- gather (+ tf32 round) ----------------
__global__ void gather_kernel(const float* __restrict__ X, const float* __restrict__ X1,
                              const int* __restrict__ pos,
                              float* __restrict__ Xg, float* __restrict__ X1g) {
    int p = blockIdx.x, tid = threadIdx.x;
    int r = pos[p];
    float4 v0 = ((const float4*)(X  + (long long)r * HH))[tid];
    float4 v1 = ((const float4*)(X1 + (long long)r * HH))[tid];
    v0.x = f2tf_f(v0.x); v0.y = f2tf_f(v0.y); v0.z = f2tf_f(v0.z); v0.w = f2tf_f(v0.w);
    v1.x = f2tf_f(v1.x); v1.y = f2tf_f(v1.y); v1.z = f2tf_f(v1.z); v1.w = f2tf_f(v1.w);
    ((float4*)(Xg  + (long long)p * HH))[tid] = v0;
    ((float4*)(X1g + (long long)p * HH))[tid] = v1;
}

// ---------------- round weights to tf32 ----------------
__global__ void round_w_kernel(const float* __restrict__ W1, const float* __restrict__ W2,
                               const float* __restrict__ W3, float* __restrict__ Wd) {
    long long i = ((long long)blockIdx.x * 256 + threadIdx.x);     // float4 index
    const long long per = (long long)AA * HH * HH / 4;
    const float4* src = (i < per) ? (const float4*)W1
                       : (i < 2 * per) ? (const float4*)W2 : (const float4*)W3;
    long long off = i % per;
    float4 v = src[off];
    v.x = f2tf_f(v.x); v.y = f2tf_f(v.y); v.z = f2tf_f(v.z); v.w = f2tf_f(v.w);
    ((float4*)Wd)[i] = v;
}

// ---------------- prep: gw = gamma*W4 ; Gco = sum gamma*W4 ; Bco = sum beta*W4 + b4 ----------------
__global__ void prep_kernel(const float* __restrict__ gamma, const float* __restrict__ beta,
                            const float* __restrict__ W4, const float* __restrict__ b4,
                            float* __restrict__ gw, float* __restrict__ Gco, float* __restrict__ Bco) {
    __shared__ float red[8][256];
    int a = blockIdx.x, tid = threadIdx.x;
    float G[4] = {0, 0, 0, 0}, Bc[4] = {0, 0, 0, 0};
    for (int h = tid; h < HH; h += 256) {
        float g = gamma[a * HH + h], be = beta[a * HH + h];
        float4 w = *(const float4*)&W4[((long long)a * HH + h) * 4];
        float4 r = make_float4(g * w.x, g * w.y, g * w.z, g * w.w);
        *(float4*)&gw[((long long)a * HH + h) * 4] = r;
        G[0] += r.x; G[1] += r.y; G[2] += r.z; G[3] += r.w;
        Bc[0] += be * w.x; Bc[1] += be * w.y; Bc[2] += be * w.z; Bc[3] += be * w.w;
    }
#pragma unroll
    for (int j = 0; j < 4; ++j) { red[j][tid] = G[j]; red[4 + j][tid] = Bc[j]; }
    __syncthreads();
    for (int s = 128; s > 0; s >>= 1) {
        if (tid < s)
#pragma unroll
            for (int j = 0; j < 8; ++j) red[j][tid] += red[j][tid + s];
        __syncthreads();
    }
    if (tid < 4) {
        Gco[a * 4 + tid] = red[tid][0];
        Bco[a * 4 + tid] = red[4 + tid][0] + b4[a * 4 + tid];
    }
}

// ---------------- tf32 mma.sync GEMM, 3-stage cp.async pipeline ----------------
template <bool DUAL, bool REDUCE>
__global__ void __launch_bounds__(256, 2)
gemm_mma(const float* __restrict__ A1, const float* __restrict__ A2,
         const float* __restrict__ B1, const float* __restrict__ B2,
         long long strideA,
         const float* __restrict__ bias1, const float* __restrict__ bias2,
         const float* __restrict__ gw,
         float* __restrict__ outZ, float* __restrict__ part) {
    extern __shared__ float sm[];
    float* Asb[NST];
    float* Bsb[NST];
    uint32_t sA[NST], sB[NST];
#pragma unroll
    for (int s = 0; s < NST; ++s) {
        Asb[s] = sm + s * ASZ;
        Bsb[s] = sm + NST * ASZ + s * BSZ;
        sA[s] = smem_u32(Asb[s]);
        sB[s] = smem_u32(Bsb[s]);
    }

    const int tid = threadIdx.x, lane = tid & 31, wid = tid >> 5;
    const int g = lane >> 2, t = lane & 3;
    const int wm = (wid >> 2) * 64, wn = (wid & 3) * 32;
    const int m0 = blockIdx.x * BM, n0 = blockIdx.y * BN, a = blockIdx.z;
    const int NIT = DUAL ? 64 : 32;

    float c[4][4][4];
#pragma unroll
    for (int i = 0; i < 4; ++i)
#pragma unroll
        for (int j = 0; j < 4; ++j)
#pragma unroll
            for (int q = 0; q < 4; ++q) c[i][j][q] = 0.f;

    auto load_stage = [&](int it) {
        int buf = it % NST;
        int pr = DUAL ? (it >> 5) : 0;
        int k0 = DUAL ? (it & 31) * BK : it * BK;
        const float* Ag = DUAL ? (pr ? A2 : A1) : (A1 + (long long)a * strideA);
        const float* Bg = ((DUAL && pr) ? B2 : B1) + (long long)a * HH * HH;
#pragma unroll
        for (int u = 0; u < 4; ++u) {
            int idx = tid + u * 256;
            int m = idx >> 3, kq = idx & 7;
            cp16(sA[buf] + (uint32_t)(m * 36 + kq * 4) * 4,
                 Ag + (long long)(m0 + m) * HH + k0 + kq * 4);
        }
#pragma unroll
        for (int u = 0; u < 4; ++u) {
            int idx = tid + u * 256;
            int k = idx >> 5, nq = idx & 31;
            cp16(sB[buf] + (uint32_t)(k * 132 + nq * 4) * 4,
                 Bg + (long long)(k0 + k) * HH + n0 + nq * 4);
        }
        cp_commit();
    };

    load_stage(0);
    load_stage(1);
#pragma unroll 1
    for (int it = 0; it < NIT; ++it) {
        if (it == NIT - 1) cp_wait<0>();
        else               cp_wait<1>();
        __syncthreads();                 // stage it visible; all warps done with stage it-1
        if (it + 2 < NIT) load_stage(it + 2);   // overwrites buffer (it-1)%NST — safe

        int buf = it % NST;
        const float* As = Asb[buf];
        const float* Bs = Bsb[buf];
#pragma unroll
        for (int ks = 0; ks < 4; ++ks) {
            uint32_t af[4][4], bf[4][2];
#pragma unroll
            for (int i = 0; i < 4; ++i) {
                int r0 = wm + i * 16 + g;
                int col = ks * 8 + t;
                af[i][0] = __float_as_uint(As[r0 * 36 + col]);
                af[i][1] = __float_as_uint(As[(r0 + 8) * 36 + col]);
                af[i][2] = __float_as_uint(As[r0 * 36 + col + 4]);
                af[i][3] = __float_as_uint(As[(r0 + 8) * 36 + col + 4]);
            }
#pragma unroll
            for (int j = 0; j < 4; ++j) {
                int nn = wn + j * 8 + g;
                bf[j][0] = __float_as_uint(Bs[(ks * 8 + t) * 132 + nn]);
                bf[j][1] = __float_as_uint(Bs[(ks * 8 + t + 4) * 132 + nn]);
            }
#pragma unroll
            for (int i = 0; i < 4; ++i)
#pragma unroll
                for (int j = 0; j < 4; ++j) mma_tf32(c[i][j], af[i], bf[j]);
        }
    }
    __syncthreads();

    if (!REDUCE) {
        // epilogue: + (b1+b2), round to tf32, store Z
#pragma unroll
        for (int j = 0; j < 4; ++j) {
            int col = n0 + wn + j * 8 + t * 2;
            float bx = bias1[a * HH + col]     + bias2[a * HH + col];
            float by = bias1[a * HH + col + 1] + bias2[a * HH + col + 1];
#pragma unroll
            for (int i = 0; i < 4; ++i) {
                int row = m0 + wm + i * 16 + g;
                float2 v0 = make_float2(f2tf_f(c[i][j][0] + bx), f2tf_f(c[i][j][1] + by));
                float2 v1 = make_float2(f2tf_f(c[i][j][2] + bx), f2tf_f(c[i][j][3] + by));
                *(float2*)&outZ[((long long)a * PP + row) * HH + col]     = v0;
                *(float2*)&outZ[((long long)a * PP + row + 8) * HH + col] = v1;
            }
        }
    } else {
        // epilogue: v = relu(c + b3); partials s1=sum v, s2=sum v^2, s3=sum v*gw
        float* red = sm;
        for (int idx = tid; idx < 128 * 8; idx += 256) red[idx] = 0.f;
        __syncthreads();
#pragma unroll
        for (int i = 0; i < 4; ++i) {
#pragma unroll
            for (int gs = 0; gs < 2; ++gs) {
                float s1 = 0.f, s2 = 0.f, sx = 0.f, sy = 0.f, sz = 0.f, sw = 0.f;
#pragma unroll
                for (int j = 0; j < 4; ++j) {
                    int col = n0 + wn + j * 8 + t * 2;
                    float v0 = fmaxf(c[i][j][gs * 2]     + bias1[a * HH + col],     0.f);
                    float v1 = fmaxf(c[i][j][gs * 2 + 1] + bias1[a * HH + col + 1], 0.f);
                    s1 += v0 + v1;
                    s2 += v0 * v0 + v1 * v1;
                    float4 g0 = *(const float4*)&gw[((long long)a * HH + col) * 4];
                    float4 g1 = *(const float4*)&gw[((long long)a * HH + col + 1) * 4];
                    sx += v0 * g0.x + v1 * g1.x;
                    sy += v0 * g0.y + v1 * g1.y;
                    sz += v0 * g0.z + v1 * g1.z;
                    sw += v0 * g0.w + v1 * g1.w;
                }
#pragma unroll
                for (int o = 1; o <= 2; o <<= 1) {
                    s1 += __shfl_xor_sync(0xFFFFFFFFu, s1, o);
                    s2 += __shfl_xor_sync(0xFFFFFFFFu, s2, o);
                    sx += __shfl_xor_sync(0xFFFFFFFFu, sx, o);
                    sy += __shfl_xor_sync(0xFFFFFFFFu, sy, o);
                    sz += __shfl_xor_sync(0xFFFFFFFFu, sz, o);
                    sw += __shfl_xor_sync(0xFFFFFFFFu, sw, o);
                }
                if (t == 0) {
                    int rl = wm + i * 16 + gs * 8 + g;
                    atomicAdd(&red[rl * 8 + 0], s1);
                    atomicAdd(&red[rl * 8 + 1], s2);
                    atomicAdd(&red[rl * 8 + 2], sx);
                    atomicAdd(&red[rl * 8 + 3], sy);
                    atomicAdd(&red[rl * 8 + 4], sz);
                    atomicAdd(&red[rl * 8 + 5], sw);
                }
            }
        }
        __syncthreads();
        for (int idx = tid; idx < 128 * 6; idx += 256) {
            int row = idx / 6, q = idx % 6;
            part[(((long long)a * 8 + blockIdx.y) * PP + (m0 + row)) * 8 + q] = red[row * 8 + q];
        }
    }
}

// ---------------- final: combine partials, closed-form LN + projection ----------------
__global__ void final_kernel(const float* __restrict__ part, const float* __restrict__ Gco,
                             const float* __restrict__ Bco, float* __restrict__ out) {
    int tk = blockIdx.x * 256 + threadIdx.x;
    int p = tk >> 4, a = tk & 15;
    float s1 = 0.f, s2 = 0.f, so[4] = {0.f, 0.f, 0.f, 0.f};
#pragma unroll
    for (int nt = 0; nt < 8; ++nt) {
        const float* q = part + (((long long)a * 8 + nt) * PP + p) * 8;
        s1 += q[0]; s2 += q[1];
        so[0] += q[2]; so[1] += q[3]; so[2] += q[4]; so[3] += q[5];
    }
    float mu  = s1 * (1.0f / HH);
    float var = s2 * (1.0f / HH) - mu * mu;
    float inv = rsqrtf(var + 1e-5f);
    float4 o;
    o.x = (so[0] - mu * Gco[a * 4 + 0]) * inv + Bco[a * 4 + 0];
    o.y = (so[1] - mu * Gco[a * 4 + 1]) * inv + Bco[a * 4 + 1];
    o.z = (so[2] - mu * Gco[a * 4 + 2]) * inv + Bco[a * 4 + 2];
    o.w = (so[3] - mu * Gco[a * 4 + 3]) * inv + Bco[a * 4 + 3];
    ((float4*)out)[tk] = o;
}

// ---------------- host ----------------
extern "C" void kernel_launch(void* const* d_in, const int* in_sizes, int n_in,
                              void* d_out, int out_size) {
    const float* X     = (const float*)d_in[0];
    const float* X1    = (const float*)d_in[1];
    const float* W1    = (const float*)d_in[2];
    const float* b1    = (const float*)d_in[3];
    const float* W2    = (const float*)d_in[4];
    const float* b2    = (const float*)d_in[5];
    const float* W3    = (const float*)d_in[6];
    const float* b3    = (const float*)d_in[7];
    const float* gamma = (const float*)d_in[8];
    const float* beta  = (const float*)d_in[9];
    const float* W4    = (const float*)d_in[10];
    const float* b4    = (const float*)d_in[11];
    const int*   pos   = (const int*)d_in[12];
    float* out = (float*)d_out;

    float *pXg, *pX1g, *pW, *pZ, *pgw, *pGco, *pBco, *ppart;
    cudaGetSymbolAddress((void**)&pXg,   g_Xg);
    cudaGetSymbolAddress((void**)&pX1g,  g_X1g);
    cudaGetSymbolAddress((void**)&pW,    g_W);
    cudaGetSymbolAddress((void**)&pZ,    g_Z);
    cudaGetSymbolAddress((void**)&pgw,   g_gw);
    cudaGetSymbolAddress((void**)&pGco,  g_Gco);
    cudaGetSymbolAddress((void**)&pBco,  g_Bco);
    cudaGetSymbolAddress((void**)&ppart, g_part);

    cudaFuncSetAttribute(gemm_mma<true,  false>, cudaFuncAttributeMaxDynamicSharedMemorySize, SMEM_BYTES);
    cudaFuncSetAttribute(gemm_mma<false, true >, cudaFuncAttributeMaxDynamicSharedMemorySize, SMEM_BYTES);

    gather_kernel<<<PP, 256>>>(X, X1, pos, pXg, pX1g);
    {
        long long nq = 3ll * AA * HH * HH / 4;
        round_w_kernel<<<(unsigned)(nq / 256), 256>>>(W1, W2, W3, pW);
    }
    prep_kernel<<<AA, 256>>>(gamma, beta, W4, b4, pgw, pGco, pBco);

    const float* W1r = pW;
    const float* W2r = pW + 1ll * AA * HH * HH;
    const float* W3r = pW + 2ll * AA * HH * HH;

    dim3 gg(PP / BM, HH / BN, AA);
    gemm_mma<true, false><<<gg, 256, SMEM_BYTES>>>(
        pXg, pX1g, W1r, W2r, 0LL, b1, b2, nullptr, pZ, nullptr);
    gemm_mma<false, true><<<gg, 256, SMEM_BYTES>>>(
        pZ, nullptr, W3r, nullptr, (long long)PP * HH, b3, nullptr, pgw, nullptr, ppart);
    final_kernel<<<(PP * AA) / 256, 256>>>(ppart, pGco, pBco, out);
}

// round 6
// speedup vs baseline: 1.4766x; 1.4766x over previous
#include <cuda_runtime.h>
#include <cstdint>

#define PP 2048
#define HH 1024
#define AA 16
#define OO 4

#define BM 128
#define BN 128
#define BK 32
#define NST 3
#define TILE 4096                      // floats per stage tile (128x32 or 32x128)

#define SMEM_FLOATS (NST * 2 * TILE)   // 24576 floats = 96KB
#define SMEM_BYTES  (SMEM_FLOATS * 4)

typedef long long ll;

// ---------------- device scratch (all permuted fragment-major) ----------------
__device__ float g_Xg [PP * HH];                      // [mtile16][ktile32][4096]
__device__ float g_X1g[PP * HH];
__device__ float g_W  [3ll * AA * HH * HH];           // [(w*16+a)*8+ntile][ktile32][4096]
__device__ float g_Z  [(ll)AA * PP * HH];             // [(a*16+mtile)*32+ktile][4096]
__device__ float g_gw [AA * HH * OO];
__device__ float g_Gco[AA * OO];
__device__ float g_Bco[AA * OO];
__device__ float g_part[(ll)AA * 8 * PP * 8];         // [a][ntile][p][8]

// ---------------- helpers ----------------
__device__ __forceinline__ uint32_t smem_u32(const void* p) {
    uint32_t a;
    asm("{ .reg .u64 t; cvta.to.shared.u64 t, %1; cvt.u32.u64 %0, t; }" : "=r"(a) : "l"(p));
    return a;
}
__device__ __forceinline__ void cp16(uint32_t s, const void* g) {
    asm volatile("cp.async.cg.shared.global [%0], [%1], 16;" :: "r"(s), "l"(g));
}
__device__ __forceinline__ void cp_commit() {
    asm volatile("cp.async.commit_group;" ::: "memory");
}
template <int N>
__device__ __forceinline__ void cp_wait() {
    asm volatile("cp.async.wait_group %0;" :: "n"(N) : "memory");
}
__device__ __forceinline__ float f2tf_f(float v) {
    uint32_t r;
    asm("cvt.rna.tf32.f32 %0, %1;" : "=r"(r) : "f"(v));
    return __uint_as_float(r);
}
__device__ __forceinline__ void mma_tf32(float c[4], const uint32_t a[4], const uint32_t b[2]) {
    asm volatile(
        "mma.sync.aligned.m16n8k8.row.col.f32.tf32.tf32.f32 "
        "{%0,%1,%2,%3}, {%4,%5,%6,%7}, {%8,%9}, {%0,%1,%2,%3};"
        : "+f"(c[0]), "+f"(c[1]), "+f"(c[2]), "+f"(c[3])
        : "r"(a[0]), "r"(a[1]), "r"(a[2]), "r"(a[3]), "r"(b[0]), "r"(b[1]));
}

// ---------------- gather: X rows -> permuted A tiles (tf32-rounded) ----------------
// grid (16 mtile, 32 ktile), block 256
__global__ void gather_kernel(const float* __restrict__ X, const float* __restrict__ X1,
                              const int* __restrict__ pos,
                              float* __restrict__ Xg, float* __restrict__ X1g) {
    __shared__ float s0[128 * 36];
    __shared__ float s1[128 * 36];
    int mt = blockIdx.x, kt = blockIdx.y, tid = threadIdx.x;
    int row = tid >> 1, half = tid & 1;
    int r = pos[mt * 128 + row];
    const float4* px  = (const float4*)(X  + (ll)r * HH + kt * 32 + half * 16);
    const float4* px1 = (const float4*)(X1 + (ll)r * HH + kt * 32 + half * 16);
#pragma unroll
    for (int u = 0; u < 4; ++u) {
        float4 v = px[u];
        v.x = f2tf_f(v.x); v.y = f2tf_f(v.y); v.z = f2tf_f(v.z); v.w = f2tf_f(v.w);
        *(float4*)&s0[row * 36 + half * 16 + u * 4] = v;
        float4 w = px1[u];
        w.x = f2tf_f(w.x); w.y = f2tf_f(w.y); w.z = f2tf_f(w.z); w.w = f2tf_f(w.w);
        *(float4*)&s1[row * 36 + half * 16 + u * 4] = w;
    }
    __syncthreads();
    float4* o0 = (float4*)(Xg  + (ll)(mt * 32 + kt) * TILE);
    float4* o1 = (float4*)(X1g + (ll)(mt * 32 + kt) * TILE);
#pragma unroll
    for (int c = 0; c < 4; ++c) {
        int chunk = tid + c * 256;
        int wm2 = chunk >> 9, i = (chunk >> 7) & 3, ks = (chunk >> 5) & 3, lane = chunk & 31;
        int g = lane >> 2, t = lane & 3;
        int r0 = wm2 * 64 + i * 16, col = ks * 8;
        o0[chunk] = make_float4(s0[(r0 + g) * 36 + col + t],     s0[(r0 + 8 + g) * 36 + col + t],
                                s0[(r0 + g) * 36 + col + t + 4], s0[(r0 + 8 + g) * 36 + col + t + 4]);
        o1[chunk] = make_float4(s1[(r0 + g) * 36 + col + t],     s1[(r0 + 8 + g) * 36 + col + t],
                                s1[(r0 + g) * 36 + col + t + 4], s1[(r0 + 8 + g) * 36 + col + t + 4]);
    }
}

// ---------------- round + permute weights: W[a][k][n] -> fragment-major B tiles ----------------
// grid (8 ntile, 32 ktile, 48 w*a), block 256
__global__ void round_w_kernel(const float* __restrict__ W1, const float* __restrict__ W2,
                               const float* __restrict__ W3, float* __restrict__ Wd) {
    __shared__ float sw[32 * 132];
    int nt = blockIdx.x, kt = blockIdx.y, wa = blockIdx.z;
    int w = wa >> 4, a = wa & 15, tid = threadIdx.x;
    const float* src = (w == 0 ? W1 : (w == 1 ? W2 : W3)) + (ll)a * HH * HH;
    int row = tid >> 3, colq = (tid & 7) * 16;
    const float4* ps = (const float4*)(src + (ll)(kt * 32 + row) * HH + nt * 128 + colq);
#pragma unroll
    for (int u = 0; u < 4; ++u) {
        float4 v = ps[u];
        v.x = f2tf_f(v.x); v.y = f2tf_f(v.y); v.z = f2tf_f(v.z); v.w = f2tf_f(v.w);
        *(float4*)&sw[row * 132 + colq + u * 4] = v;
    }
    __syncthreads();
    float2* op = (float2*)(Wd + (((ll)(w * 16 + a) * 8 + nt) * 32 + kt) * TILE);
#pragma unroll
    for (int c = 0; c < 8; ++c) {
        int chunk = tid + c * 256;
        int wn4 = chunk >> 9, j = (chunk >> 7) & 3, ks = (chunk >> 5) & 3, lane = chunk & 31;
        int g = lane >> 2, t = lane & 3;
        int n_loc = wn4 * 32 + j * 8 + g, k_lo = ks * 8 + t;
        op[chunk] = make_float2(sw[k_lo * 132 + n_loc], sw[(k_lo + 4) * 132 + n_loc]);
    }
}

// ---------------- prep: gw = gamma*W4 ; Gco = sum gamma*W4 ; Bco = sum beta*W4 + b4 ----------------
__global__ void prep_kernel(const float* __restrict__ gamma, const float* __restrict__ beta,
                            const float* __restrict__ W4, const float* __restrict__ b4,
                            float* __restrict__ gw, float* __restrict__ Gco, float* __restrict__ Bco) {
    __shared__ float red[8][256];
    int a = blockIdx.x, tid = threadIdx.x;
    float G[4] = {0, 0, 0, 0}, Bc[4] = {0, 0, 0, 0};
    for (int h = tid; h < HH; h += 256) {
        float g = gamma[a * HH + h], be = beta[a * HH + h];
        float4 w = *(const float4*)&W4[((ll)a * HH + h) * 4];
        float4 r = make_float4(g * w.x, g * w.y, g * w.z, g * w.w);
        *(float4*)&gw[((ll)a * HH + h) * 4] = r;
        G[0] += r.x; G[1] += r.y; G[2] += r.z; G[3] += r.w;
        Bc[0] += be * w.x; Bc[1] += be * w.y; Bc[2] += be * w.z; Bc[3] += be * w.w;
    }
#pragma unroll
    for (int j = 0; j < 4; ++j) { red[j][tid] = G[j]; red[4 + j][tid] = Bc[j]; }
    __syncthreads();
    for (int s = 128; s > 0; s >>= 1) {
        if (tid < s)
#pragma unroll
            for (int j = 0; j < 8; ++j) red[j][tid] += red[j][tid + s];
        __syncthreads();
    }
    if (tid < 4) {
        Gco[a * 4 + tid] = red[tid][0];
        Bco[a * 4 + tid] = red[4 + tid][0] + b4[a * 4 + tid];
    }
}

// ---------------- tf32 mma.sync GEMM, fragment-major SMEM, 3-stage cp.async ----------------
template <bool DUAL, bool REDUCE>
__global__ void __launch_bounds__(256, 2)
gemm_mma(const float* __restrict__ A1, const float* __restrict__ A2,
         const float* __restrict__ B1, const float* __restrict__ B2,
         const float* __restrict__ bias1, const float* __restrict__ bias2,
         const float* __restrict__ gw,
         float* __restrict__ outZ, float* __restrict__ part) {
    extern __shared__ float sm[];
    const int tid = threadIdx.x, lane = tid & 31, wid = tid >> 5;
    const int g = lane >> 2, t = lane & 3;
    const int wm2 = wid >> 2, wn4 = wid & 3;
    const int wm = wm2 * 64, wn = wn4 * 32;
    const int bx = blockIdx.x, by = blockIdx.y, a = blockIdx.z;
    const int m0 = bx * BM, n0 = by * BN;
    const int NIT = DUAL ? 64 : 32;

    uint32_t sA[NST], sB[NST];
#pragma unroll
    for (int s = 0; s < NST; ++s) {
        sA[s] = smem_u32(sm + s * TILE);
        sB[s] = smem_u32(sm + (NST + s) * TILE);
    }

    float c[4][4][4];
#pragma unroll
    for (int i = 0; i < 4; ++i)
#pragma unroll
        for (int j = 0; j < 4; ++j)
#pragma unroll
            for (int q = 0; q < 4; ++q) c[i][j][q] = 0.f;

    auto load_stage = [&](int it) {
        int buf = it % NST;
        int pr = DUAL ? (it >> 5) : 0;
        int kt = DUAL ? (it & 31) : it;
        const float* Ag = DUAL ? ((pr ? A2 : A1) + ((ll)bx * 32 + kt) * TILE)
                               : (A1 + (((ll)(a * 16 + bx)) * 32 + kt) * TILE);
        const float* Bg = ((DUAL && pr) ? B2 : B1) + (((ll)(a * 8 + by)) * 32 + kt) * TILE;
#pragma unroll
        for (int u = 0; u < 4; ++u) {
            int idx = tid + u * 256;
            cp16(sA[buf] + (uint32_t)idx * 16, Ag + idx * 4);
        }
#pragma unroll
        for (int u = 0; u < 4; ++u) {
            int idx = tid + u * 256;
            cp16(sB[buf] + (uint32_t)idx * 16, Bg + idx * 4);
        }
        cp_commit();
    };

    load_stage(0);
    load_stage(1);
#pragma unroll 1
    for (int it = 0; it < NIT; ++it) {
        if (it == NIT - 1) cp_wait<0>();
        else               cp_wait<1>();
        __syncthreads();
        if (it + 2 < NIT) load_stage(it + 2);

        int buf = it % NST;
        const float4* A4 = (const float4*)(sm + buf * TILE);
        const float2* B2v = (const float2*)(sm + (NST + buf) * TILE);
#pragma unroll
        for (int ks = 0; ks < 4; ++ks) {
            uint32_t af[4][4], bf[4][2];
#pragma unroll
            for (int i = 0; i < 4; ++i) {
                float4 v = A4[((wm2 * 4 + i) * 4 + ks) * 32 + lane];
                af[i][0] = __float_as_uint(v.x); af[i][1] = __float_as_uint(v.y);
                af[i][2] = __float_as_uint(v.z); af[i][3] = __float_as_uint(v.w);
            }
#pragma unroll
            for (int j = 0; j < 4; ++j) {
                float2 w = B2v[((wn4 * 4 + j) * 4 + ks) * 32 + lane];
                bf[j][0] = __float_as_uint(w.x); bf[j][1] = __float_as_uint(w.y);
            }
#pragma unroll
            for (int i = 0; i < 4; ++i)
#pragma unroll
                for (int j = 0; j < 4; ++j) mma_tf32(c[i][j], af[i], bf[j]);
        }
    }
    __syncthreads();

    if (!REDUCE) {
        // epilogue: +(b1+b2), round tf32, stage in SMEM, write Z as permuted A tiles
        float* Cs = sm;   // [128][132]
#pragma unroll
        for (int j = 0; j < 4; ++j) {
            int col = wn + j * 8 + t * 2;
            int gc = n0 + col;
            float bx0 = bias1[a * HH + gc]     + bias2[a * HH + gc];
            float by0 = bias1[a * HH + gc + 1] + bias2[a * HH + gc + 1];
#pragma unroll
            for (int i = 0; i < 4; ++i) {
                int r0 = wm + i * 16 + g;
                Cs[r0 * 132 + col]           = f2tf_f(c[i][j][0] + bx0);
                Cs[r0 * 132 + col + 1]       = f2tf_f(c[i][j][1] + by0);
                Cs[(r0 + 8) * 132 + col]     = f2tf_f(c[i][j][2] + bx0);
                Cs[(r0 + 8) * 132 + col + 1] = f2tf_f(c[i][j][3] + by0);
            }
        }
        __syncthreads();
#pragma unroll
        for (int ktl = 0; ktl < 4; ++ktl) {
            float4* op = (float4*)(outZ + (((ll)(a * 16 + bx)) * 32 + by * 4 + ktl) * TILE);
#pragma unroll
            for (int cc = 0; cc < 4; ++cc) {
                int chunk = tid + cc * 256;
                int pm2 = chunk >> 9, pi = (chunk >> 7) & 3, pks = (chunk >> 5) & 3, pl = chunk & 31;
                int pg = pl >> 2, pt = pl & 3;
                int r0 = pm2 * 64 + pi * 16, col = ktl * 32 + pks * 8;
                op[chunk] = make_float4(Cs[(r0 + pg) * 132 + col + pt],
                                        Cs[(r0 + 8 + pg) * 132 + col + pt],
                                        Cs[(r0 + pg) * 132 + col + pt + 4],
                                        Cs[(r0 + 8 + pg) * 132 + col + pt + 4]);
            }
        }
    } else {
        // epilogue: v = relu(c + b3); partials s1, s2, s3 = sum v*gw
        float* red = sm;
        for (int idx = tid; idx < 128 * 8; idx += 256) red[idx] = 0.f;
        __syncthreads();
#pragma unroll
        for (int i = 0; i < 4; ++i) {
#pragma unroll
            for (int gs = 0; gs < 2; ++gs) {
                float s1 = 0.f, s2 = 0.f, sx = 0.f, sy = 0.f, sz = 0.f, sw = 0.f;
#pragma unroll
                for (int j = 0; j < 4; ++j) {
                    int col = n0 + wn + j * 8 + t * 2;
                    float v0 = fmaxf(c[i][j][gs * 2]     + bias1[a * HH + col],     0.f);
                    float v1 = fmaxf(c[i][j][gs * 2 + 1] + bias1[a * HH + col + 1], 0.f);
                    s1 += v0 + v1;
                    s2 += v0 * v0 + v1 * v1;
                    float4 g0 = *(const float4*)&gw[((ll)a * HH + col) * 4];
                    float4 g1 = *(const float4*)&gw[((ll)a * HH + col + 1) * 4];
                    sx += v0 * g0.x + v1 * g1.x;
                    sy += v0 * g0.y + v1 * g1.y;
                    sz += v0 * g0.z + v1 * g1.z;
                    sw += v0 * g0.w + v1 * g1.w;
                }
#pragma unroll
                for (int o = 1; o <= 2; o <<= 1) {
                    s1 += __shfl_xor_sync(0xFFFFFFFFu, s1, o);
                    s2 += __shfl_xor_sync(0xFFFFFFFFu, s2, o);
                    sx += __shfl_xor_sync(0xFFFFFFFFu, sx, o);
                    sy += __shfl_xor_sync(0xFFFFFFFFu, sy, o);
                    sz += __shfl_xor_sync(0xFFFFFFFFu, sz, o);
                    sw += __shfl_xor_sync(0xFFFFFFFFu, sw, o);
                }
                if (t == 0) {
                    int rl = wm + i * 16 + gs * 8 + g;
                    atomicAdd(&red[rl * 8 + 0], s1);
                    atomicAdd(&red[rl * 8 + 1], s2);
                    atomicAdd(&red[rl * 8 + 2], sx);
                    atomicAdd(&red[rl * 8 + 3], sy);
                    atomicAdd(&red[rl * 8 + 4], sz);
                    atomicAdd(&red[rl * 8 + 5], sw);
                }
            }
        }
        __syncthreads();
        for (int idx = tid; idx < 128 * 6; idx += 256) {
            int row = idx / 6, q = idx % 6;
            part[(((ll)a * 8 + by) * PP + (m0 + row)) * 8 + q] = red[row * 8 + q];
        }
    }
}

// ---------------- final: combine partials, closed-form LN + projection ----------------
__global__ void final_kernel(const float* __restrict__ part, const float* __restrict__ Gco,
                             const float* __restrict__ Bco, float* __restrict__ out) {
    int tk = blockIdx.x * 256 + threadIdx.x;
    int p = tk >> 4, a = tk & 15;
    float s1 = 0.f, s2 = 0.f, so[4] = {0.f, 0.f, 0.f, 0.f};
#pragma unroll
    for (int nt = 0; nt < 8; ++nt) {
        const float* q = part + (((ll)a * 8 + nt) * PP + p) * 8;
        s1 += q[0]; s2 += q[1];
        so[0] += q[2]; so[1] += q[3]; so[2] += q[4]; so[3] += q[5];
    }
    float mu  = s1 * (1.0f / HH);
    float var = s2 * (1.0f / HH) - mu * mu;
    float inv = rsqrtf(var + 1e-5f);
    float4 o;
    o.x = (so[0] - mu * Gco[a * 4 + 0]) * inv + Bco[a * 4 + 0];
    o.y = (so[1] - mu * Gco[a * 4 + 1]) * inv + Bco[a * 4 + 1];
    o.z = (so[2] - mu * Gco[a * 4 + 2]) * inv + Bco[a * 4 + 2];
    o.w = (so[3] - mu * Gco[a * 4 + 3]) * inv + Bco[a * 4 + 3];
    ((float4*)out)[tk] = o;
}

// ---------------- host ----------------
extern "C" void kernel_launch(void* const* d_in, const int* in_sizes, int n_in,
                              void* d_out, int out_size) {
    const float* X     = (const float*)d_in[0];
    const float* X1    = (const float*)d_in[1];
    const float* W1    = (const float*)d_in[2];
    const float* b1    = (const float*)d_in[3];
    const float* W2    = (const float*)d_in[4];
    const float* b2    = (const float*)d_in[5];
    const float* W3    = (const float*)d_in[6];
    const float* b3    = (const float*)d_in[7];
    const float* gamma = (const float*)d_in[8];
    const float* beta  = (const float*)d_in[9];
    const float* W4    = (const float*)d_in[10];
    const float* b4    = (const float*)d_in[11];
    const int*   pos   = (const int*)d_in[12];
    float* out = (float*)d_out;

    float *pXg, *pX1g, *pW, *pZ, *pgw, *pGco, *pBco, *ppart;
    cudaGetSymbolAddress((void**)&pXg,   g_Xg);
    cudaGetSymbolAddress((void**)&pX1g,  g_X1g);
    cudaGetSymbolAddress((void**)&pW,    g_W);
    cudaGetSymbolAddress((void**)&pZ,    g_Z);
    cudaGetSymbolAddress((void**)&pgw,   g_gw);
    cudaGetSymbolAddress((void**)&pGco,  g_Gco);
    cudaGetSymbolAddress((void**)&pBco,  g_Bco);
    cudaGetSymbolAddress((void**)&ppart, g_part);

    cudaFuncSetAttribute(gemm_mma<true,  false>, cudaFuncAttributeMaxDynamicSharedMemorySize, SMEM_BYTES);
    cudaFuncSetAttribute(gemm_mma<false, true >, cudaFuncAttributeMaxDynamicSharedMemorySize, SMEM_BYTES);

    gather_kernel<<<dim3(PP / BM, 32), 256>>>(X, X1, pos, pXg, pX1g);
    round_w_kernel<<<dim3(8, 32, 48), 256>>>(W1, W2, W3, pW);
    prep_kernel<<<AA, 256>>>(gamma, beta, W4, b4, pgw, pGco, pBco);

    const float* W1r = pW;
    const float* W2r = pW + 1ll * AA * HH * HH;
    const float* W3r = pW + 2ll * AA * HH * HH;

    dim3 gg(PP / BM, HH / BN, AA);
    gemm_mma<true, false><<<gg, 256, SMEM_BYTES>>>(
        pXg, pX1g, W1r, W2r, b1, b2, nullptr, pZ, nullptr);
    gemm_mma<false, true><<<gg, 256, SMEM_BYTES>>>(
        pZ, nullptr, W3r, nullptr, b3, nullptr, pgw, nullptr, ppart);
    final_kernel<<<(PP * AA) / 256, 256>>>(ppart, pGco, pBco, out);
}

// round 7
// speedup vs baseline: 1.5186x; 1.0285x over previous
#include <cuda_runtime.h>
#include <cstdint>

#define PP 2048
#define HH 1024
#define AA 16
#define OO 4

#define BM 128
#define BN 128
#define BK 32
#define NST 3
#define TILE 4096                      // floats per stage tile (128x32 or 32x128)

#define SMEM_FLOATS (NST * 2 * TILE)   // 24576 floats = 96KB
#define SMEM_BYTES  (SMEM_FLOATS * 4)

typedef long long ll;

// ---------------- device scratch (all permuted fragment-major) ----------------
__device__ float g_Xg [PP * HH];                      // [mtile16][ktile32][4096]
__device__ float g_X1g[PP * HH];
__device__ float g_W  [3ll * AA * HH * HH];           // [(w*16+a)*8+ntile][ktile32][4096]
__device__ float g_Z  [(ll)AA * PP * HH];             // [(a*16+mtile)*32+ktile][4096]
__device__ float g_gw [AA * HH * OO];
__device__ float g_Gco[AA * OO];
__device__ float g_Bco[AA * OO];
__device__ float g_part[(ll)AA * 8 * PP * 8];         // [a][ntile][p][8]

// ---------------- helpers ----------------
__device__ __forceinline__ uint32_t smem_u32(const void* p) {
    uint32_t a;
    asm("{ .reg .u64 t; cvta.to.shared.u64 t, %1; cvt.u32.u64 %0, t; }" : "=r"(a) : "l"(p));
    return a;
}
__device__ __forceinline__ void cp16(uint32_t s, const void* g) {
    asm volatile("cp.async.cg.shared.global [%0], [%1], 16;" :: "r"(s), "l"(g));
}
__device__ __forceinline__ void cp_commit() {
    asm volatile("cp.async.commit_group;" ::: "memory");
}
template <int N>
__device__ __forceinline__ void cp_wait() {
    asm volatile("cp.async.wait_group %0;" :: "n"(N) : "memory");
}
__device__ __forceinline__ float f2tf_f(float v) {
    uint32_t r;
    asm("cvt.rna.tf32.f32 %0, %1;" : "=r"(r) : "f"(v));
    return __uint_as_float(r);
}
__device__ __forceinline__ void mma_tf32(float c[4], const uint32_t a[4], const uint32_t b[2]) {
    asm volatile(
        "mma.sync.aligned.m16n8k8.row.col.f32.tf32.tf32.f32 "
        "{%0,%1,%2,%3}, {%4,%5,%6,%7}, {%8,%9}, {%0,%1,%2,%3};"
        : "+f"(c[0]), "+f"(c[1]), "+f"(c[2]), "+f"(c[3])
        : "r"(a[0]), "r"(a[1]), "r"(a[2]), "r"(a[3]), "r"(b[0]), "r"(b[1]));
}

// ---------------- gather: X rows -> permuted A tiles (tf32-rounded) ----------------
__global__ void gather_kernel(const float* __restrict__ X, const float* __restrict__ X1,
                              const int* __restrict__ pos,
                              float* __restrict__ Xg, float* __restrict__ X1g) {
    __shared__ float s0[128 * 36];
    __shared__ float s1[128 * 36];
    int mt = blockIdx.x, kt = blockIdx.y, tid = threadIdx.x;
    int row = tid >> 1, half = tid & 1;
    int r = pos[mt * 128 + row];
    const float4* px  = (const float4*)(X  + (ll)r * HH + kt * 32 + half * 16);
    const float4* px1 = (const float4*)(X1 + (ll)r * HH + kt * 32 + half * 16);
#pragma unroll
    for (int u = 0; u < 4; ++u) {
        float4 v = px[u];
        v.x = f2tf_f(v.x); v.y = f2tf_f(v.y); v.z = f2tf_f(v.z); v.w = f2tf_f(v.w);
        *(float4*)&s0[row * 36 + half * 16 + u * 4] = v;
        float4 w = px1[u];
        w.x = f2tf_f(w.x); w.y = f2tf_f(w.y); w.z = f2tf_f(w.z); w.w = f2tf_f(w.w);
        *(float4*)&s1[row * 36 + half * 16 + u * 4] = w;
    }
    __syncthreads();
    float4* o0 = (float4*)(Xg  + (ll)(mt * 32 + kt) * TILE);
    float4* o1 = (float4*)(X1g + (ll)(mt * 32 + kt) * TILE);
#pragma unroll
    for (int c = 0; c < 4; ++c) {
        int chunk = tid + c * 256;
        int wm2 = chunk >> 9, i = (chunk >> 7) & 3, ks = (chunk >> 5) & 3, lane = chunk & 31;
        int g = lane >> 2, t = lane & 3;
        int r0 = wm2 * 64 + i * 16, col = ks * 8;
        o0[chunk] = make_float4(s0[(r0 + g) * 36 + col + t],     s0[(r0 + 8 + g) * 36 + col + t],
                                s0[(r0 + g) * 36 + col + t + 4], s0[(r0 + 8 + g) * 36 + col + t + 4]);
        o1[chunk] = make_float4(s1[(r0 + g) * 36 + col + t],     s1[(r0 + 8 + g) * 36 + col + t],
                                s1[(r0 + g) * 36 + col + t + 4], s1[(r0 + 8 + g) * 36 + col + t + 4]);
    }
}

// ---------------- round + permute weights: W[a][k][n] -> fragment-major B tiles ----------------
__global__ void round_w_kernel(const float* __restrict__ W1, const float* __restrict__ W2,
                               const float* __restrict__ W3, float* __restrict__ Wd) {
    __shared__ float sw[32 * 132];
    int nt = blockIdx.x, kt = blockIdx.y, wa = blockIdx.z;
    int w = wa >> 4, a = wa & 15, tid = threadIdx.x;
    const float* src = (w == 0 ? W1 : (w == 1 ? W2 : W3)) + (ll)a * HH * HH;
    int row = tid >> 3, colq = (tid & 7) * 16;
    const float4* ps = (const float4*)(src + (ll)(kt * 32 + row) * HH + nt * 128 + colq);
#pragma unroll
    for (int u = 0; u < 4; ++u) {
        float4 v = ps[u];
        v.x = f2tf_f(v.x); v.y = f2tf_f(v.y); v.z = f2tf_f(v.z); v.w = f2tf_f(v.w);
        *(float4*)&sw[row * 132 + colq + u * 4] = v;
    }
    __syncthreads();
    float2* op = (float2*)(Wd + (((ll)(w * 16 + a) * 8 + nt) * 32 + kt) * TILE);
#pragma unroll
    for (int c = 0; c < 8; ++c) {
        int chunk = tid + c * 256;
        int wn4 = chunk >> 9, j = (chunk >> 7) & 3, ks = (chunk >> 5) & 3, lane = chunk & 31;
        int g = lane >> 2, t = lane & 3;
        int n_loc = wn4 * 32 + j * 8 + g, k_lo = ks * 8 + t;
        op[chunk] = make_float2(sw[k_lo * 132 + n_loc], sw[(k_lo + 4) * 132 + n_loc]);
    }
}

// ---------------- prep: gw = gamma*W4 ; Gco = sum gamma*W4 ; Bco = sum beta*W4 + b4 ----------------
__global__ void prep_kernel(const float* __restrict__ gamma, const float* __restrict__ beta,
                            const float* __restrict__ W4, const float* __restrict__ b4,
                            float* __restrict__ gw, float* __restrict__ Gco, float* __restrict__ Bco) {
    __shared__ float red[8][256];
    int a = blockIdx.x, tid = threadIdx.x;
    float G[4] = {0, 0, 0, 0}, Bc[4] = {0, 0, 0, 0};
    for (int h = tid; h < HH; h += 256) {
        float g = gamma[a * HH + h], be = beta[a * HH + h];
        float4 w = *(const float4*)&W4[((ll)a * HH + h) * 4];
        float4 r = make_float4(g * w.x, g * w.y, g * w.z, g * w.w);
        *(float4*)&gw[((ll)a * HH + h) * 4] = r;
        G[0] += r.x; G[1] += r.y; G[2] += r.z; G[3] += r.w;
        Bc[0] += be * w.x; Bc[1] += be * w.y; Bc[2] += be * w.z; Bc[3] += be * w.w;
    }
#pragma unroll
    for (int j = 0; j < 4; ++j) { red[j][tid] = G[j]; red[4 + j][tid] = Bc[j]; }
    __syncthreads();
    for (int s = 128; s > 0; s >>= 1) {
        if (tid < s)
#pragma unroll
            for (int j = 0; j < 8; ++j) red[j][tid] += red[j][tid + s];
        __syncthreads();
    }
    if (tid < 4) {
        Gco[a * 4 + tid] = red[tid][0];
        Bco[a * 4 + tid] = red[4 + tid][0] + b4[a * 4 + tid];
    }
}

// ---------------- tf32 mma.sync GEMM, fragment-major SMEM, 3-stage cp.async ----------------
template <bool DUAL, bool REDUCE>
__global__ void __launch_bounds__(256, 2)
gemm_mma(const float* __restrict__ A1, const float* __restrict__ A2,
         const float* __restrict__ B1, const float* __restrict__ B2,
         const float* __restrict__ bias1, const float* __restrict__ bias2,
         const float* __restrict__ gw,
         float* __restrict__ outZ, float* __restrict__ part) {
    extern __shared__ float sm[];
    const int tid = threadIdx.x, lane = tid & 31, wid = tid >> 5;
    const int g = lane >> 2, t = lane & 3;
    const int wm2 = wid >> 2, wn4 = wid & 3;
    const int wm = wm2 * 64, wn = wn4 * 32;
    const int bx = blockIdx.x, by = blockIdx.y, a = blockIdx.z;
    const int m0 = bx * BM, n0 = by * BN;
    const int NIT = DUAL ? 64 : 32;

    // Precomputed per-buffer smem addresses (dst for cp.async, src for frags)
    uint32_t dA[NST], dB[NST];
    const float4* A4b[NST];
    const float2* B2b[NST];
#pragma unroll
    for (int s = 0; s < NST; ++s) {
        dA[s] = smem_u32(sm + s * TILE) + (uint32_t)tid * 16;
        dB[s] = smem_u32(sm + (NST + s) * TILE) + (uint32_t)tid * 16;
        A4b[s] = (const float4*)(sm + s * TILE);
        B2b[s] = (const float2*)(sm + (NST + s) * TILE);
    }

    // Global tile bases (per-thread offset folded in)
    const float* Ag0 = (DUAL ? A1 + (ll)bx * 32 * TILE
                             : A1 + ((ll)(a * 16 + bx)) * 32 * TILE) + tid * 4;
    const float* Bg0 = B1 + ((ll)(a * 8 + by)) * 32 * TILE + tid * 4;
    const float* Ag1 = DUAL ? A2 + (ll)bx * 32 * TILE + tid * 4 : nullptr;
    const float* Bg1 = DUAL ? B2 + ((ll)(a * 8 + by)) * 32 * TILE + tid * 4 : nullptr;

    float c[4][4][4];
#pragma unroll
    for (int i = 0; i < 4; ++i)
#pragma unroll
        for (int j = 0; j < 4; ++j)
#pragma unroll
            for (int q = 0; q < 4; ++q) c[i][j][q] = 0.f;

    auto load_stage = [&](int buf, int it) {
        const float* Ag = (DUAL && it >= 32) ? Ag1 + (it - 32) * TILE : Ag0 + it * TILE;
        const float* Bg = (DUAL && it >= 32) ? Bg1 + (it - 32) * TILE : Bg0 + it * TILE;
#pragma unroll
        for (int u = 0; u < 4; ++u) cp16(dA[buf] + u * 4096, Ag + u * 1024);
#pragma unroll
        for (int u = 0; u < 4; ++u) cp16(dB[buf] + u * 4096, Bg + u * 1024);
        cp_commit();
    };

    load_stage(0, 0);
    load_stage(1, 1);
    int buf = 0, buf2 = 2;   // compute buffer; buffer to fill with it+2
#pragma unroll 1
    for (int it = 0; it < NIT; ++it) {
        if (it == NIT - 1) cp_wait<0>();
        else               cp_wait<1>();
        __syncthreads();

        const float4* A4 = A4b[buf];
        const float2* B2v = B2b[buf];

        // ---- ks = 0: fragments + MMAs first, then kick next TMA burst ----
        uint32_t af[4][4], bf[4][2];
#pragma unroll
        for (int i = 0; i < 4; ++i) {
            float4 v = A4[((wm2 * 4 + i) * 4 + 0) * 32 + lane];
            af[i][0] = __float_as_uint(v.x); af[i][1] = __float_as_uint(v.y);
            af[i][2] = __float_as_uint(v.z); af[i][3] = __float_as_uint(v.w);
        }
#pragma unroll
        for (int j = 0; j < 4; ++j) {
            float2 w = B2v[((wn4 * 4 + j) * 4 + 0) * 32 + lane];
            bf[j][0] = __float_as_uint(w.x); bf[j][1] = __float_as_uint(w.y);
        }
#pragma unroll
        for (int i = 0; i < 4; ++i)
#pragma unroll
            for (int j = 0; j < 4; ++j) mma_tf32(c[i][j], af[i], bf[j]);

        if (it + 2 < NIT) load_stage(buf2, it + 2);   // overlapped with tensor work

#pragma unroll
        for (int ks = 1; ks < 4; ++ks) {
#pragma unroll
            for (int i = 0; i < 4; ++i) {
                float4 v = A4[((wm2 * 4 + i) * 4 + ks) * 32 + lane];
                af[i][0] = __float_as_uint(v.x); af[i][1] = __float_as_uint(v.y);
                af[i][2] = __float_as_uint(v.z); af[i][3] = __float_as_uint(v.w);
            }
#pragma unroll
            for (int j = 0; j < 4; ++j) {
                float2 w = B2v[((wn4 * 4 + j) * 4 + ks) * 32 + lane];
                bf[j][0] = __float_as_uint(w.x); bf[j][1] = __float_as_uint(w.y);
            }
#pragma unroll
            for (int i = 0; i < 4; ++i)
#pragma unroll
                for (int j = 0; j < 4; ++j) mma_tf32(c[i][j], af[i], bf[j]);
        }

        buf  = (buf  == NST - 1) ? 0 : buf + 1;
        buf2 = (buf2 == NST - 1) ? 0 : buf2 + 1;
    }
    __syncthreads();

    if (!REDUCE) {
        // epilogue: +(b1+b2), round tf32, stage in SMEM, write Z as permuted A tiles
        float* Cs = sm;   // [128][132]
#pragma unroll
        for (int j = 0; j < 4; ++j) {
            int col = wn + j * 8 + t * 2;
            int gc = n0 + col;
            float bx0 = bias1[a * HH + gc]     + bias2[a * HH + gc];
            float by0 = bias1[a * HH + gc + 1] + bias2[a * HH + gc + 1];
#pragma unroll
            for (int i = 0; i < 4; ++i) {
                int r0 = wm + i * 16 + g;
                Cs[r0 * 132 + col]           = f2tf_f(c[i][j][0] + bx0);
                Cs[r0 * 132 + col + 1]       = f2tf_f(c[i][j][1] + by0);
                Cs[(r0 + 8) * 132 + col]     = f2tf_f(c[i][j][2] + bx0);
                Cs[(r0 + 8) * 132 + col + 1] = f2tf_f(c[i][j][3] + by0);
            }
        }
        __syncthreads();
#pragma unroll
        for (int ktl = 0; ktl < 4; ++ktl) {
            float4* op = (float4*)(outZ + (((ll)(a * 16 + bx)) * 32 + by * 4 + ktl) * TILE);
#pragma unroll
            for (int cc = 0; cc < 4; ++cc) {
                int chunk = tid + cc * 256;
                int pm2 = chunk >> 9, pi = (chunk >> 7) & 3, pks = (chunk >> 5) & 3, pl = chunk & 31;
                int pg = pl >> 2, pt = pl & 3;
                int r0 = pm2 * 64 + pi * 16, col = ktl * 32 + pks * 8;
                op[chunk] = make_float4(Cs[(r0 + pg) * 132 + col + pt],
                                        Cs[(r0 + 8 + pg) * 132 + col + pt],
                                        Cs[(r0 + pg) * 132 + col + pt + 4],
                                        Cs[(r0 + 8 + pg) * 132 + col + pt + 4]);
            }
        }
    } else {
        // epilogue: v = relu(c + b3); partials s1, s2, s3 = sum v*gw
        float* red = sm;
        for (int idx = tid; idx < 128 * 8; idx += 256) red[idx] = 0.f;
        __syncthreads();
#pragma unroll
        for (int i = 0; i < 4; ++i) {
#pragma unroll
            for (int gs = 0; gs < 2; ++gs) {
                float s1 = 0.f, s2 = 0.f, sx = 0.f, sy = 0.f, sz = 0.f, sw = 0.f;
#pragma unroll
                for (int j = 0; j < 4; ++j) {
                    int col = n0 + wn + j * 8 + t * 2;
                    float v0 = fmaxf(c[i][j][gs * 2]     + bias1[a * HH + col],     0.f);
                    float v1 = fmaxf(c[i][j][gs * 2 + 1] + bias1[a * HH + col + 1], 0.f);
                    s1 += v0 + v1;
                    s2 += v0 * v0 + v1 * v1;
                    float4 g0 = *(const float4*)&gw[((ll)a * HH + col) * 4];
                    float4 g1 = *(const float4*)&gw[((ll)a * HH + col + 1) * 4];
                    sx += v0 * g0.x + v1 * g1.x;
                    sy += v0 * g0.y + v1 * g1.y;
                    sz += v0 * g0.z + v1 * g1.z;
                    sw += v0 * g0.w + v1 * g1.w;
                }
#pragma unroll
                for (int o = 1; o <= 2; o <<= 1) {
                    s1 += __shfl_xor_sync(0xFFFFFFFFu, s1, o);
                    s2 += __shfl_xor_sync(0xFFFFFFFFu, s2, o);
                    sx += __shfl_xor_sync(0xFFFFFFFFu, sx, o);
                    sy += __shfl_xor_sync(0xFFFFFFFFu, sy, o);
                    sz += __shfl_xor_sync(0xFFFFFFFFu, sz, o);
                    sw += __shfl_xor_sync(0xFFFFFFFFu, sw, o);
                }
                if (t == 0) {
                    int rl = wm + i * 16 + gs * 8 + g;
                    atomicAdd(&red[rl * 8 + 0], s1);
                    atomicAdd(&red[rl * 8 + 1], s2);
                    atomicAdd(&red[rl * 8 + 2], sx);
                    atomicAdd(&red[rl * 8 + 3], sy);
                    atomicAdd(&red[rl * 8 + 4], sz);
                    atomicAdd(&red[rl * 8 + 5], sw);
                }
            }
        }
        __syncthreads();
        for (int idx = tid; idx < 128 * 6; idx += 256) {
            int row = idx / 6, q = idx % 6;
            part[(((ll)a * 8 + by) * PP + (m0 + row)) * 8 + q] = red[row * 8 + q];
        }
    }
}

// ---------------- final: combine partials, closed-form LN + projection ----------------
__global__ void final_kernel(const float* __restrict__ part, const float* __restrict__ Gco,
                             const float* __restrict__ Bco, float* __restrict__ out) {
    int tk = blockIdx.x * 256 + threadIdx.x;
    int p = tk >> 4, a = tk & 15;
    float s1 = 0.f, s2 = 0.f, so[4] = {0.f, 0.f, 0.f, 0.f};
#pragma unroll
    for (int nt = 0; nt < 8; ++nt) {
        const float* q = part + (((ll)a * 8 + nt) * PP + p) * 8;
        s1 += q[0]; s2 += q[1];
        so[0] += q[2]; so[1] += q[3]; so[2] += q[4]; so[3] += q[5];
    }
    float mu  = s1 * (1.0f / HH);
    float var = s2 * (1.0f / HH) - mu * mu;
    float inv = rsqrtf(var + 1e-5f);
    float4 o;
    o.x = (so[0] - mu * Gco[a * 4 + 0]) * inv + Bco[a * 4 + 0];
    o.y = (so[1] - mu * Gco[a * 4 + 1]) * inv + Bco[a * 4 + 1];
    o.z = (so[2] - mu * Gco[a * 4 + 2]) * inv + Bco[a * 4 + 2];
    o.w = (so[3] - mu * Gco[a * 4 + 3]) * inv + Bco[a * 4 + 3];
    ((float4*)out)[tk] = o;
}

// ---------------- host ----------------
extern "C" void kernel_launch(void* const* d_in, const int* in_sizes, int n_in,
                              void* d_out, int out_size) {
    const float* X     = (const float*)d_in[0];
    const float* X1    = (const float*)d_in[1];
    const float* W1    = (const float*)d_in[2];
    const float* b1    = (const float*)d_in[3];
    const float* W2    = (const float*)d_in[4];
    const float* b2    = (const float*)d_in[5];
    const float* W3    = (const float*)d_in[6];
    const float* b3    = (const float*)d_in[7];
    const float* gamma = (const float*)d_in[8];
    const float* beta  = (const float*)d_in[9];
    const float* W4    = (const float*)d_in[10];
    const float* b4    = (const float*)d_in[11];
    const int*   pos   = (const int*)d_in[12];
    float* out = (float*)d_out;

    float *pXg, *pX1g, *pW, *pZ, *pgw, *pGco, *pBco, *ppart;
    cudaGetSymbolAddress((void**)&pXg,   g_Xg);
    cudaGetSymbolAddress((void**)&pX1g,  g_X1g);
    cudaGetSymbolAddress((void**)&pW,    g_W);
    cudaGetSymbolAddress((void**)&pZ,    g_Z);
    cudaGetSymbolAddress((void**)&pgw,   g_gw);
    cudaGetSymbolAddress((void**)&pGco,  g_Gco);
    cudaGetSymbolAddress((void**)&pBco,  g_Bco);
    cudaGetSymbolAddress((void**)&ppart, g_part);

    cudaFuncSetAttribute(gemm_mma<true,  false>, cudaFuncAttributeMaxDynamicSharedMemorySize, SMEM_BYTES);
    cudaFuncSetAttribute(gemm_mma<false, true >, cudaFuncAttributeMaxDynamicSharedMemorySize, SMEM_BYTES);

    gather_kernel<<<dim3(PP / BM, 32), 256>>>(X, X1, pos, pXg, pX1g);
    round_w_kernel<<<dim3(8, 32, 48), 256>>>(W1, W2, W3, pW);
    prep_kernel<<<AA, 256>>>(gamma, beta, W4, b4, pgw, pGco, pBco);

    const float* W1r = pW;
    const float* W2r = pW + 1ll * AA * HH * HH;
    const float* W3r = pW + 2ll * AA * HH * HH;

    dim3 gg(PP / BM, HH / BN, AA);
    gemm_mma<true, false><<<gg, 256, SMEM_BYTES>>>(
        pXg, pX1g, W1r, W2r, b1, b2, nullptr, pZ, nullptr);
    gemm_mma<false, true><<<gg, 256, SMEM_BYTES>>>(
        pZ, nullptr, W3r, nullptr, b3, nullptr, pgw, nullptr, ppart);
    final_kernel<<<(PP * AA) / 256, 256>>>(ppart, pGco, pBco, out);
}